// round 1
// baseline (speedup 1.0000x reference)
#include <cuda_runtime.h>

#define Bn 16
#define Cc 384
#define Hh 56
#define Ww 56
#define HW (Hh*Ww)
#define KL 31
#define KS 5
#define PL 15
#define XT 86          // 56 + 2*15
#define TS 88          // padded smem row stride (floats)
#define NTHREADS 224   // 28 x 8 thread tiles of 2x7 outputs

// Scratch (device globals: allocation-free rule)
__device__ float g_yL[(size_t)Bn*Cc*HW];
__device__ float g_yS[(size_t)Bn*Cc*HW];
__device__ float g_part[4][Cc][Bn];   // sumL, sumsqL, sumS, sumsqS  (fixed slots -> deterministic)
__device__ float g_coef[4][Cc];       // scaleL, biasL, scaleS, biasS

__global__ __launch_bounds__(NTHREADS)
void conv_kernel(const float* __restrict__ x,
                 const float* __restrict__ wL,
                 const float* __restrict__ wS)
{
    __shared__ float sx[XT*TS];
    __shared__ float swL[KL*KL];
    __shared__ float swS[KS*KS];
    __shared__ float sred[2][8];

    const int blk = blockIdx.x;
    const int c = blk % Cc;
    const int n = blk / Cc;
    const int tid = threadIdx.x;

    // stage weights
    for (int i = tid; i < KL*KL; i += NTHREADS) swL[i] = wL[c*KL*KL + i];
    if (tid < KS*KS) swS[tid] = wS[c*KS*KS + tid];

    // stage input slice with zero halo
    const float* __restrict__ xp = x + (size_t)(n*Cc + c)*HW;
    for (int i = tid; i < XT*TS; i += NTHREADS) {
        int r = i / TS, col = i % TS;
        int gy = r - PL, gx = col - PL;
        float v = 0.f;
        if (col < XT && gy >= 0 && gy < Hh && gx >= 0 && gx < Ww)
            v = xp[gy*Ww + gx];
        sx[i] = v;
    }
    __syncthreads();

    const int ty = tid >> 3;       // 0..27
    const int tx = tid & 7;        // 0..7
    const int oy0 = ty*2, ox0 = tx*7;
    const int wid = tid >> 5, lane = tid & 31;

    // ---------------- large 31x31 conv ----------------
    float a0[7], a1[7];
#pragma unroll
    for (int j = 0; j < 7; j++) { a0[j] = 0.f; a1[j] = 0.f; }

#pragma unroll 1
    for (int ky = 0; ky < KL; ky++) {
        const float* __restrict__ r0 = &sx[(oy0 + ky)*TS + ox0];
        const float* __restrict__ r1 = r0 + TS;
        const float* __restrict__ wr = &swL[ky*KL];
        float w0[7], w1[7];
#pragma unroll
        for (int j = 0; j < 7; j++) { w0[j] = r0[j]; w1[j] = r1[j]; }
#pragma unroll
        for (int kx = 0; kx < KL; kx++) {
            const float w = wr[kx];
#pragma unroll
            for (int j = 0; j < 7; j++) {
                a0[j] = fmaf(w0[j], w, a0[j]);
                a1[j] = fmaf(w1[j], w, a1[j]);
            }
            if (kx < KL-1) {
#pragma unroll
                for (int j = 0; j < 6; j++) { w0[j] = w0[j+1]; w1[j] = w1[j+1]; }
                w0[6] = r0[kx+7];
                w1[6] = r1[kx+7];
            }
        }
    }

    // write yL + per-block stats
    {
        float* __restrict__ yp = g_yL + (size_t)(n*Cc + c)*HW;
        float s = 0.f, q = 0.f;
#pragma unroll
        for (int j = 0; j < 7; j++) {
            yp[oy0*Ww + ox0 + j]     = a0[j];
            yp[(oy0+1)*Ww + ox0 + j] = a1[j];
            s += a0[j] + a1[j];
            q += a0[j]*a0[j] + a1[j]*a1[j];
        }
#pragma unroll
        for (int o = 16; o; o >>= 1) {
            s += __shfl_down_sync(0xFFFFFFFFu, s, o);
            q += __shfl_down_sync(0xFFFFFFFFu, q, o);
        }
        if (lane == 0) { sred[0][wid] = s; sred[1][wid] = q; }
        __syncthreads();
        if (tid == 0) {
            float S = 0.f, Q = 0.f;
            for (int i = 0; i < 7; i++) { S += sred[0][i]; Q += sred[1][i]; }
            g_part[0][c][n] = S;
            g_part[1][c][n] = Q;
        }
        __syncthreads();   // sred reused below
    }

    // ---------------- small 5x5 conv ----------------
    float b0[7], b1[7];
#pragma unroll
    for (int j = 0; j < 7; j++) { b0[j] = 0.f; b1[j] = 0.f; }

#pragma unroll
    for (int ky = 0; ky < KS; ky++) {
        // out(oy,ox) needs x[oy+ky-2][ox+kx-2] -> smem row oy+ky+13, col ox+kx+13
        const float* __restrict__ r0 = &sx[(oy0 + ky + 13)*TS + ox0 + 13];
        const float* __restrict__ r1 = r0 + TS;
        float v0[11], v1[11];
#pragma unroll
        for (int j = 0; j < 11; j++) { v0[j] = r0[j]; v1[j] = r1[j]; }
        const float* __restrict__ wr = &swS[ky*KS];
#pragma unroll
        for (int kx = 0; kx < KS; kx++) {
            const float w = wr[kx];
#pragma unroll
            for (int j = 0; j < 7; j++) {
                b0[j] = fmaf(v0[kx+j], w, b0[j]);
                b1[j] = fmaf(v1[kx+j], w, b1[j]);
            }
        }
    }

    // write yS + per-block stats
    {
        float* __restrict__ yp = g_yS + (size_t)(n*Cc + c)*HW;
        float s = 0.f, q = 0.f;
#pragma unroll
        for (int j = 0; j < 7; j++) {
            yp[oy0*Ww + ox0 + j]     = b0[j];
            yp[(oy0+1)*Ww + ox0 + j] = b1[j];
            s += b0[j] + b1[j];
            q += b0[j]*b0[j] + b1[j]*b1[j];
        }
#pragma unroll
        for (int o = 16; o; o >>= 1) {
            s += __shfl_down_sync(0xFFFFFFFFu, s, o);
            q += __shfl_down_sync(0xFFFFFFFFu, q, o);
        }
        if (lane == 0) { sred[0][wid] = s; sred[1][wid] = q; }
        __syncthreads();
        if (tid == 0) {
            float S = 0.f, Q = 0.f;
            for (int i = 0; i < 7; i++) { S += sred[0][i]; Q += sred[1][i]; }
            g_part[2][c][n] = S;
            g_part[3][c][n] = Q;
        }
    }
}

__global__ void stats_kernel(const float* __restrict__ gammaL, const float* __restrict__ betaL,
                             const float* __restrict__ gammaS, const float* __restrict__ betaS)
{
    int c = blockIdx.x*blockDim.x + threadIdx.x;
    if (c >= Cc) return;
    const float Nf = (float)(Bn*HW);
    float sL = 0.f, qL = 0.f, sS = 0.f, qS = 0.f;
#pragma unroll
    for (int n = 0; n < Bn; n++) {
        sL += g_part[0][c][n]; qL += g_part[1][c][n];
        sS += g_part[2][c][n]; qS += g_part[3][c][n];
    }
    float mL = sL / Nf, vL = qL / Nf - mL*mL;
    float invL = rsqrtf(vL + 1e-5f);
    float scL = gammaL[c] * invL;
    g_coef[0][c] = scL;
    g_coef[1][c] = betaL[c] - mL*scL;

    float mS = sS / Nf, vS = qS / Nf - mS*mS;
    float invS = rsqrtf(vS + 1e-5f);
    float scS = gammaS[c] * invS;
    g_coef[2][c] = scS;
    g_coef[3][c] = betaS[c] - mS*scS;
}

__global__ void norm_kernel(float* __restrict__ out)
{
    const int total4 = Bn*Cc*HW/4;
    int i = blockIdx.x*blockDim.x + threadIdx.x;
    if (i >= total4) return;
    const int c = (i / (HW/4)) % Cc;
    const float4 a = reinterpret_cast<const float4*>(g_yL)[i];
    const float4 b = reinterpret_cast<const float4*>(g_yS)[i];
    const float scL = g_coef[0][c], bL = g_coef[1][c];
    const float scS = g_coef[2][c], bS = g_coef[3][c];
    float4 o;
    o.x = fmaf(a.x, scL, bL) + fmaf(b.x, scS, bS);
    o.y = fmaf(a.y, scL, bL) + fmaf(b.y, scS, bS);
    o.z = fmaf(a.z, scL, bL) + fmaf(b.z, scS, bS);
    o.w = fmaf(a.w, scL, bL) + fmaf(b.w, scS, bS);
    reinterpret_cast<float4*>(out)[i] = o;
}

extern "C" void kernel_launch(void* const* d_in, const int* in_sizes, int n_in,
                              void* d_out, int out_size)
{
    const float* x       = (const float*)d_in[0];
    const float* w_large = (const float*)d_in[1];
    const float* gammaL  = (const float*)d_in[2];
    const float* betaL   = (const float*)d_in[3];
    const float* w_small = (const float*)d_in[4];
    const float* gammaS  = (const float*)d_in[5];
    const float* betaS   = (const float*)d_in[6];
    float* out = (float*)d_out;

    conv_kernel<<<Bn*Cc, NTHREADS>>>(x, w_large, w_small);
    stats_kernel<<<(Cc + 127)/128, 128>>>(gammaL, betaL, gammaS, betaS);
    const int total4 = Bn*Cc*HW/4;
    norm_kernel<<<(total4 + 255)/256, 256>>>(out);
}

// round 2
// speedup vs baseline: 1.0976x; 1.0976x over previous
#include <cuda_runtime.h>

#define Bn 16
#define Cc 384
#define Hh 56
#define Ww 56
#define HW (Hh*Ww)
#define KL 31
#define KS 5
#define PL 15
#define XT 86          // 56 + 2*15
#define TS 92          // smem row stride in float2 elements (TS%8==4 -> conflict-free)
#define NTHREADS 224   // 28 row-groups (2 rows) x 8 col-groups (7 cols)
#define NWARPS 7

typedef unsigned long long ull;

// Scratch (device globals: allocation-free rule)
__device__ float g_yL[(size_t)Bn*Cc*HW];
__device__ float g_yS[(size_t)Bn*Cc*HW];
__device__ float g_part[4][Cc][Bn];   // sumL, sumsqL, sumS, sumsqS
__device__ float g_coef[4][Cc];       // scaleL, biasL, scaleS, biasS

__device__ __forceinline__ ull f2fma(ull a, ull b, ull c) {
    ull d;
    asm("fma.rn.f32x2 %0, %1, %2, %3;" : "=l"(d) : "l"(a), "l"(b), "l"(c));
    return d;
}
__device__ __forceinline__ float2 u2f(ull v) {
    float2 f;
    asm("mov.b64 {%0, %1}, %2;" : "=f"(f.x), "=f"(f.y) : "l"(v));
    return f;
}
__device__ __forceinline__ ull f2u(float x, float y) {
    ull v;
    asm("mov.b64 %0, {%1, %2};" : "=l"(v) : "f"(x), "f"(y));
    return v;
}

// dynamic smem layout (bytes):
//   sx   : XT*TS ull        = 63296
//   swL2 : KL*KL ull        = 7688
//   swS2 : KS*KS ull        = 200
//   sred : 4*NWARPS float   = 112
#define SMEM_BYTES (XT*TS*8 + KL*KL*8 + KS*KS*8 + 4*NWARPS*4)

__global__ __launch_bounds__(NTHREADS, 3)
void conv_kernel(const float* __restrict__ x,
                 const float* __restrict__ wL,
                 const float* __restrict__ wS)
{
    extern __shared__ ull dyn[];
    ull* sx   = dyn;                 // [XT*TS] interleaved {imgA, imgB}
    ull* swL2 = sx + XT*TS;          // [KL*KL] {w,w}
    ull* swS2 = swL2 + KL*KL;        // [KS*KS] {w,w}
    float* sred = (float*)(swS2 + KS*KS);  // [4][NWARPS]

    const int blk = blockIdx.x;
    const int c  = blk % Cc;
    const int np = blk / Cc;
    const int nA = np*2;
    const int tid = threadIdx.x;

    // stage weights duplicated {w,w}
    for (int i = tid; i < KL*KL; i += NTHREADS) {
        float w = wL[c*KL*KL + i];
        swL2[i] = f2u(w, w);
    }
    if (tid < KS*KS) {
        float w = wS[c*KS*KS + tid];
        swS2[tid] = f2u(w, w);
    }

    // stage both image slices interleaved, zero halo
    const float* __restrict__ xA = x + (size_t)(nA*Cc + c)*HW;
    const float* __restrict__ xB = xA + (size_t)Cc*HW;
    for (int i = tid; i < XT*TS; i += NTHREADS) {
        int r = i / TS, col = i % TS;
        int gy = r - PL, gx = col - PL;
        float a = 0.f, b = 0.f;
        if (col < XT && gy >= 0 && gy < Hh && gx >= 0 && gx < Ww) {
            a = xA[gy*Ww + gx];
            b = xB[gy*Ww + gx];
        }
        sx[i] = f2u(a, b);
    }
    __syncthreads();

    const int ty = tid >> 3;       // 0..27
    const int tx = tid & 7;        // 0..7
    const int oy0 = ty*2, ox0 = tx*7;
    const int wid = tid >> 5, lane = tid & 31;

    // ---------------- large 31x31 conv (packed over 2 images) ----------------
    ull a0[7], a1[7];
#pragma unroll
    for (int j = 0; j < 7; j++) { a0[j] = 0ULL; a1[j] = 0ULL; }

#pragma unroll 1
    for (int ky = 0; ky < KL; ky++) {
        const ull* __restrict__ r0 = sx + (oy0 + ky)*TS + ox0;
        const ull* __restrict__ r1 = r0 + TS;
        const ull* __restrict__ wr = swL2 + ky*KL;

        ull win0[8], win1[8];
#pragma unroll
        for (int j = 0; j < 7; j++) { win0[j] = r0[j]; win1[j] = r1[j]; }
        ull wcur = wr[0];
#pragma unroll
        for (int kx = 0; kx < KL; kx++) {
            ull wnext = (kx < KL-1) ? wr[kx+1] : 0ULL;
#pragma unroll
            for (int j = 0; j < 7; j++) {
                int idx = (kx + j) & 7;
                a0[j] = f2fma(win0[idx], wcur, a0[j]);
                a1[j] = f2fma(win1[idx], wcur, a1[j]);
            }
            if (kx < KL-1) {
                win0[(kx+7)&7] = r0[kx+7];
                win1[(kx+7)&7] = r1[kx+7];
            }
            wcur = wnext;
        }
    }

    // write yL (both images) + per-block stats
    {
        float* __restrict__ ypA = g_yL + (size_t)(nA*Cc + c)*HW;
        float* __restrict__ ypB = ypA + (size_t)Cc*HW;
        float sA = 0.f, qA = 0.f, sB = 0.f, qB = 0.f;
#pragma unroll
        for (int j = 0; j < 7; j++) {
            float2 v0 = u2f(a0[j]);
            float2 v1 = u2f(a1[j]);
            ypA[oy0*Ww + ox0 + j]     = v0.x;
            ypA[(oy0+1)*Ww + ox0 + j] = v1.x;
            ypB[oy0*Ww + ox0 + j]     = v0.y;
            ypB[(oy0+1)*Ww + ox0 + j] = v1.y;
            sA += v0.x + v1.x;  qA += v0.x*v0.x + v1.x*v1.x;
            sB += v0.y + v1.y;  qB += v0.y*v0.y + v1.y*v1.y;
        }
#pragma unroll
        for (int o = 16; o; o >>= 1) {
            sA += __shfl_down_sync(0xFFFFFFFFu, sA, o);
            qA += __shfl_down_sync(0xFFFFFFFFu, qA, o);
            sB += __shfl_down_sync(0xFFFFFFFFu, sB, o);
            qB += __shfl_down_sync(0xFFFFFFFFu, qB, o);
        }
        if (lane == 0) {
            sred[0*NWARPS + wid] = sA;
            sred[1*NWARPS + wid] = qA;
            sred[2*NWARPS + wid] = sB;
            sred[3*NWARPS + wid] = qB;
        }
        __syncthreads();
        if (tid == 0) {
            float SA=0,QA=0,SB=0,QB=0;
            for (int i = 0; i < NWARPS; i++) {
                SA += sred[0*NWARPS+i]; QA += sred[1*NWARPS+i];
                SB += sred[2*NWARPS+i]; QB += sred[3*NWARPS+i];
            }
            g_part[0][c][nA]   = SA;  g_part[1][c][nA]   = QA;
            g_part[0][c][nA+1] = SB;  g_part[1][c][nA+1] = QB;
        }
        __syncthreads();   // sred reused below
    }

    // ---------------- small 5x5 conv (packed) ----------------
    ull b0[7], b1[7];
#pragma unroll
    for (int j = 0; j < 7; j++) { b0[j] = 0ULL; b1[j] = 0ULL; }

#pragma unroll
    for (int ky = 0; ky < KS; ky++) {
        const ull* __restrict__ r0 = sx + (oy0 + ky + 13)*TS + ox0 + 13;
        const ull* __restrict__ r1 = r0 + TS;
        ull v0[11], v1[11];
#pragma unroll
        for (int j = 0; j < 11; j++) { v0[j] = r0[j]; v1[j] = r1[j]; }
        const ull* __restrict__ wr = swS2 + ky*KS;
#pragma unroll
        for (int kx = 0; kx < KS; kx++) {
            ull w = wr[kx];
#pragma unroll
            for (int j = 0; j < 7; j++) {
                b0[j] = f2fma(v0[kx+j], w, b0[j]);
                b1[j] = f2fma(v1[kx+j], w, b1[j]);
            }
        }
    }

    // write yS + per-block stats
    {
        float* __restrict__ ypA = g_yS + (size_t)(nA*Cc + c)*HW;
        float* __restrict__ ypB = ypA + (size_t)Cc*HW;
        float sA = 0.f, qA = 0.f, sB = 0.f, qB = 0.f;
#pragma unroll
        for (int j = 0; j < 7; j++) {
            float2 v0 = u2f(b0[j]);
            float2 v1 = u2f(b1[j]);
            ypA[oy0*Ww + ox0 + j]     = v0.x;
            ypA[(oy0+1)*Ww + ox0 + j] = v1.x;
            ypB[oy0*Ww + ox0 + j]     = v0.y;
            ypB[(oy0+1)*Ww + ox0 + j] = v1.y;
            sA += v0.x + v1.x;  qA += v0.x*v0.x + v1.x*v1.x;
            sB += v0.y + v1.y;  qB += v0.y*v0.y + v1.y*v1.y;
        }
#pragma unroll
        for (int o = 16; o; o >>= 1) {
            sA += __shfl_down_sync(0xFFFFFFFFu, sA, o);
            qA += __shfl_down_sync(0xFFFFFFFFu, qA, o);
            sB += __shfl_down_sync(0xFFFFFFFFu, sB, o);
            qB += __shfl_down_sync(0xFFFFFFFFu, qB, o);
        }
        if (lane == 0) {
            sred[0*NWARPS + wid] = sA;
            sred[1*NWARPS + wid] = qA;
            sred[2*NWARPS + wid] = sB;
            sred[3*NWARPS + wid] = qB;
        }
        __syncthreads();
        if (tid == 0) {
            float SA=0,QA=0,SB=0,QB=0;
            for (int i = 0; i < NWARPS; i++) {
                SA += sred[0*NWARPS+i]; QA += sred[1*NWARPS+i];
                SB += sred[2*NWARPS+i]; QB += sred[3*NWARPS+i];
            }
            g_part[2][c][nA]   = SA;  g_part[3][c][nA]   = QA;
            g_part[2][c][nA+1] = SB;  g_part[3][c][nA+1] = QB;
        }
    }
}

__global__ void stats_kernel(const float* __restrict__ gammaL, const float* __restrict__ betaL,
                             const float* __restrict__ gammaS, const float* __restrict__ betaS)
{
    int c = blockIdx.x*blockDim.x + threadIdx.x;
    if (c >= Cc) return;
    const float Nf = (float)(Bn*HW);
    float sL = 0.f, qL = 0.f, sS = 0.f, qS = 0.f;
#pragma unroll
    for (int n = 0; n < Bn; n++) {
        sL += g_part[0][c][n]; qL += g_part[1][c][n];
        sS += g_part[2][c][n]; qS += g_part[3][c][n];
    }
    float mL = sL / Nf, vL = qL / Nf - mL*mL;
    float invL = rsqrtf(vL + 1e-5f);
    float scL = gammaL[c] * invL;
    g_coef[0][c] = scL;
    g_coef[1][c] = betaL[c] - mL*scL;

    float mS = sS / Nf, vS = qS / Nf - mS*mS;
    float invS = rsqrtf(vS + 1e-5f);
    float scS = gammaS[c] * invS;
    g_coef[2][c] = scS;
    g_coef[3][c] = betaS[c] - mS*scS;
}

__global__ void norm_kernel(float* __restrict__ out)
{
    const int total4 = Bn*Cc*HW/4;
    int i = blockIdx.x*blockDim.x + threadIdx.x;
    if (i >= total4) return;
    const int c = (i / (HW/4)) % Cc;
    const float4 a = reinterpret_cast<const float4*>(g_yL)[i];
    const float4 b = reinterpret_cast<const float4*>(g_yS)[i];
    const float scL = g_coef[0][c], bL = g_coef[1][c];
    const float scS = g_coef[2][c], bS = g_coef[3][c];
    float4 o;
    o.x = fmaf(a.x, scL, bL) + fmaf(b.x, scS, bS);
    o.y = fmaf(a.y, scL, bL) + fmaf(b.y, scS, bS);
    o.z = fmaf(a.z, scL, bL) + fmaf(b.z, scS, bS);
    o.w = fmaf(a.w, scL, bL) + fmaf(b.w, scS, bS);
    reinterpret_cast<float4*>(out)[i] = o;
}

extern "C" void kernel_launch(void* const* d_in, const int* in_sizes, int n_in,
                              void* d_out, int out_size)
{
    const float* x       = (const float*)d_in[0];
    const float* w_large = (const float*)d_in[1];
    const float* gammaL  = (const float*)d_in[2];
    const float* betaL   = (const float*)d_in[3];
    const float* w_small = (const float*)d_in[4];
    const float* gammaS  = (const float*)d_in[5];
    const float* betaS   = (const float*)d_in[6];
    float* out = (float*)d_out;

    cudaFuncSetAttribute(conv_kernel, cudaFuncAttributeMaxDynamicSharedMemorySize, SMEM_BYTES);
    conv_kernel<<<(Bn/2)*Cc, NTHREADS, SMEM_BYTES>>>(x, w_large, w_small);
    stats_kernel<<<(Cc + 127)/128, 128>>>(gammaL, betaL, gammaS, betaS);
    const int total4 = Bn*Cc*HW/4;
    norm_kernel<<<(total4 + 255)/256, 256>>>(out);
}